// round 1
// baseline (speedup 1.0000x reference)
#include <cuda_runtime.h>
#include <math.h>

// Problem constants (fixed shapes from reference setup)
#define NP 512      // N memory rows
#define MP 512      // M query rows
#define DD 1024     // feature dim
#define H1C 512     // layer1 width
#define H2C 256     // layer2 width
#define NPAIR (NP*MP)  // 262144

// Scratch (module-load allocated; allowed per harness rules)
__device__ float g_h1[(size_t)NPAIR * H1C];   // 512 MB
__device__ float g_h2[(size_t)NPAIR * H2C];   // 256 MB
__device__ float g_d[NPAIR];                  // 1 MB logits
__device__ float g_cost[NPAIR];               // 1 MB

__device__ __forceinline__ float lrelu(float x) {
    return x >= 0.f ? x : 0.01f * x;
}

// ---------------------------------------------------------------------------
// Layer 1: h1[r, h] = lrelu( sum_d (Maug[n,d]-Q[m,d])^2 * W1[h,d] + b1[h] )
// r = n*512 + m.  GEMM 262144 x 512, K=1024.  Block tile 128x128, BK=16.
// A tile generated on the fly from Maug / Q.
// ---------------------------------------------------------------------------
__global__ __launch_bounds__(256) void k_layer1(
    const float* __restrict__ Maug, const float* __restrict__ Q,
    const float* __restrict__ W1, const float* __restrict__ b1)
{
    __shared__ float As[16][128];
    __shared__ float Bs[16][128];

    const int by = blockIdx.y;           // row block 0..2047
    const int bx = blockIdx.x;           // col block 0..3
    const int n  = by >> 2;              // 128-row tile never straddles n
    const int m0 = (by & 3) * 128;
    const int h0 = bx * 128;
    const int tid = threadIdx.x;
    const int tx = tid & 15;             // col dir
    const int ty = tid >> 4;             // row dir

    float acc[8][8];
#pragma unroll
    for (int i = 0; i < 8; i++)
#pragma unroll
        for (int j = 0; j < 8; j++) acc[i][j] = 0.f;

    const float4* Q4 = (const float4*)Q;
    const float4* M4 = (const float4*)Maug;
    const float4* W4 = (const float4*)W1;

    for (int k0 = 0; k0 < DD; k0 += 16) {
        const int kq = k0 >> 2;
#pragma unroll
        for (int j = 0; j < 2; j++) {
            int idx = tid * 2 + j;           // 0..511
            int row = idx >> 2;              // 0..127
            int k4  = idx & 3;               // 0..3
            // A: diff^2 generated on the fly
            float4 q  = Q4[(m0 + row) * (DD/4) + kq + k4];
            float4 mm = M4[(size_t)n * (DD/4) + kq + k4];
            float dx = mm.x - q.x, dy = mm.y - q.y;
            float dz = mm.z - q.z, dw = mm.w - q.w;
            int kk = k4 * 4;
            As[kk+0][row] = dx*dx; As[kk+1][row] = dy*dy;
            As[kk+2][row] = dz*dz; As[kk+3][row] = dw*dw;
            // B: W1 tile (row = h index within tile)
            float4 w = W4[(h0 + row) * (DD/4) + kq + k4];
            Bs[kk+0][row] = w.x; Bs[kk+1][row] = w.y;
            Bs[kk+2][row] = w.z; Bs[kk+3][row] = w.w;
        }
        __syncthreads();

#pragma unroll
        for (int kk = 0; kk < 16; kk++) {
            float a[8], b[8];
#pragma unroll
            for (int i = 0; i < 8; i++) a[i] = As[kk][ty*8 + i];
#pragma unroll
            for (int j = 0; j < 8; j++) b[j] = Bs[kk][tx*8 + j];
#pragma unroll
            for (int i = 0; i < 8; i++)
#pragma unroll
                for (int j = 0; j < 8; j++)
                    acc[i][j] = fmaf(a[i], b[j], acc[i][j]);
        }
        __syncthreads();
    }

    // Epilogue: add bias, leaky relu, store fp32
    const int rbase = by * 128 + ty * 8;
    const int hbase = h0 + tx * 8;
    float bv[8];
#pragma unroll
    for (int j = 0; j < 8; j++) bv[j] = b1[hbase + j];
#pragma unroll
    for (int i = 0; i < 8; i++) {
        size_t off = (size_t)(rbase + i) * H1C + hbase;
        float4 o0, o1;
        o0.x = lrelu(acc[i][0] + bv[0]); o0.y = lrelu(acc[i][1] + bv[1]);
        o0.z = lrelu(acc[i][2] + bv[2]); o0.w = lrelu(acc[i][3] + bv[3]);
        o1.x = lrelu(acc[i][4] + bv[4]); o1.y = lrelu(acc[i][5] + bv[5]);
        o1.z = lrelu(acc[i][6] + bv[6]); o1.w = lrelu(acc[i][7] + bv[7]);
        *(float4*)(&g_h1[off])     = o0;
        *(float4*)(&g_h1[off + 4]) = o1;
    }
}

// ---------------------------------------------------------------------------
// cost[n,m] = sum_d (Maug[n,d]-Q[m,d])^2.  Block per n, warp per m.
// ---------------------------------------------------------------------------
__global__ __launch_bounds__(256) void k_cost(
    const float* __restrict__ Maug, const float* __restrict__ Q)
{
    __shared__ float Ms[DD];
    const int n = blockIdx.x;
    for (int i = threadIdx.x; i < DD; i += 256) Ms[i] = Maug[(size_t)n * DD + i];
    __syncthreads();
    const int warp = threadIdx.x >> 5, lane = threadIdx.x & 31;
    for (int m = warp; m < MP; m += 8) {
        const float* q = Q + (size_t)m * DD;
        float acc = 0.f;
        for (int d = lane; d < DD; d += 32) {
            float t = Ms[d] - q[d];
            acc = fmaf(t, t, acc);
        }
#pragma unroll
        for (int off = 16; off; off >>= 1)
            acc += __shfl_xor_sync(0xffffffffu, acc, off);
        if (lane == 0) g_cost[n * MP + m] = acc;
    }
}

// ---------------------------------------------------------------------------
// Layer 2: h2[r, k] = lrelu( sum_h h1[r,h] * W2[k,h] + b2[k] )
// GEMM 262144 x 256, K=512.  Same tiling.
// ---------------------------------------------------------------------------
__global__ __launch_bounds__(256) void k_layer2(
    const float* __restrict__ W2, const float* __restrict__ b2)
{
    __shared__ float As[16][128];
    __shared__ float Bs[16][128];

    const int by = blockIdx.y;           // row block 0..2047
    const int bx = blockIdx.x;           // col block 0..1
    const int r0 = by * 128;
    const int h0 = bx * 128;
    const int tid = threadIdx.x;
    const int tx = tid & 15;
    const int ty = tid >> 4;

    float acc[8][8];
#pragma unroll
    for (int i = 0; i < 8; i++)
#pragma unroll
        for (int j = 0; j < 8; j++) acc[i][j] = 0.f;

    const float4* A4 = (const float4*)g_h1;
    const float4* W4 = (const float4*)W2;

    for (int k0 = 0; k0 < H1C; k0 += 16) {
        const int kq = k0 >> 2;
#pragma unroll
        for (int j = 0; j < 2; j++) {
            int idx = tid * 2 + j;
            int row = idx >> 2;
            int k4  = idx & 3;
            float4 a = A4[(size_t)(r0 + row) * (H1C/4) + kq + k4];
            int kk = k4 * 4;
            As[kk+0][row] = a.x; As[kk+1][row] = a.y;
            As[kk+2][row] = a.z; As[kk+3][row] = a.w;
            float4 w = W4[(h0 + row) * (H1C/4) + kq + k4];
            Bs[kk+0][row] = w.x; Bs[kk+1][row] = w.y;
            Bs[kk+2][row] = w.z; Bs[kk+3][row] = w.w;
        }
        __syncthreads();
#pragma unroll
        for (int kk = 0; kk < 16; kk++) {
            float a[8], b[8];
#pragma unroll
            for (int i = 0; i < 8; i++) a[i] = As[kk][ty*8 + i];
#pragma unroll
            for (int j = 0; j < 8; j++) b[j] = Bs[kk][tx*8 + j];
#pragma unroll
            for (int i = 0; i < 8; i++)
#pragma unroll
                for (int j = 0; j < 8; j++)
                    acc[i][j] = fmaf(a[i], b[j], acc[i][j]);
        }
        __syncthreads();
    }

    const int rbase = r0 + ty * 8;
    const int hbase = h0 + tx * 8;
    float bv[8];
#pragma unroll
    for (int j = 0; j < 8; j++) bv[j] = b2[hbase + j];
#pragma unroll
    for (int i = 0; i < 8; i++) {
        size_t off = (size_t)(rbase + i) * H2C + hbase;
        float4 o0, o1;
        o0.x = lrelu(acc[i][0] + bv[0]); o0.y = lrelu(acc[i][1] + bv[1]);
        o0.z = lrelu(acc[i][2] + bv[2]); o0.w = lrelu(acc[i][3] + bv[3]);
        o1.x = lrelu(acc[i][4] + bv[4]); o1.y = lrelu(acc[i][5] + bv[5]);
        o1.z = lrelu(acc[i][6] + bv[6]); o1.w = lrelu(acc[i][7] + bv[7]);
        *(float4*)(&g_h2[off])     = o0;
        *(float4*)(&g_h2[off + 4]) = o1;
    }
}

// ---------------------------------------------------------------------------
// Layer 3: d[r] = -( sum_k W3[k]*h2[r,k] + b3 ).  Warp per row.
// ---------------------------------------------------------------------------
__global__ __launch_bounds__(256) void k_layer3(
    const float* __restrict__ W3, const float* __restrict__ b3)
{
    __shared__ float w[H2C];
    if (threadIdx.x < H2C) w[threadIdx.x] = W3[threadIdx.x];
    __syncthreads();
    const int warp = threadIdx.x >> 5, lane = threadIdx.x & 31;
    const int r = blockIdx.x * 8 + warp;
    const float* h = g_h2 + (size_t)r * H2C;
    float acc = 0.f;
#pragma unroll
    for (int k = lane; k < H2C; k += 32) acc = fmaf(w[k], h[k], acc);
#pragma unroll
    for (int off = 16; off; off >>= 1)
        acc += __shfl_xor_sync(0xffffffffu, acc, off);
    if (lane == 0) g_d[r] = -(acc + b3[0]);
}

// ---------------------------------------------------------------------------
// Softmax over n (per m) + weighted reductions.
// out[m]       = sum_n cost[n,m]*softmax_n(d)[n,m]
// out[512+m]   = sum_{n<N_fg} same
// ---------------------------------------------------------------------------
__global__ __launch_bounds__(512) void k_reduce(
    const int* __restrict__ nfg_p, float* __restrict__ out)
{
    __shared__ float sm[512];
    const int m = blockIdx.x, n = threadIdx.x;
    const float v = g_d[n * MP + m];

    sm[n] = v; __syncthreads();
    for (int s = 256; s; s >>= 1) {
        if (n < s) sm[n] = fmaxf(sm[n], sm[n + s]);
        __syncthreads();
    }
    const float mx = sm[0]; __syncthreads();

    const float p = expf(v - mx);
    sm[n] = p; __syncthreads();
    for (int s = 256; s; s >>= 1) {
        if (n < s) sm[n] += sm[n + s];
        __syncthreads();
    }
    const float Z = sm[0]; __syncthreads();

    const float sval = g_cost[n * MP + m] * (p / Z);
    sm[n] = sval; __syncthreads();
    for (int s = 256; s; s >>= 1) {
        if (n < s) sm[n] += sm[n + s];
        __syncthreads();
    }
    const float score = sm[0]; __syncthreads();

    const int nfg = *nfg_p;
    sm[n] = (n < nfg) ? sval : 0.f; __syncthreads();
    for (int s = 256; s; s >>= 1) {
        if (n < s) sm[n] += sm[n + s];
        __syncthreads();
    }
    if (n == 0) {
        out[m]      = score;
        out[MP + m] = sm[0];
    }
}

// ---------------------------------------------------------------------------
extern "C" void kernel_launch(void* const* d_in, const int* in_sizes, int n_in,
                              void* d_out, int out_size)
{
    const float* Maug = (const float*)d_in[0];
    const float* Q    = (const float*)d_in[1];
    const float* W1   = (const float*)d_in[2];
    const float* b1   = (const float*)d_in[3];
    const float* W2   = (const float*)d_in[4];
    const float* b2   = (const float*)d_in[5];
    const float* W3   = (const float*)d_in[6];
    const float* b3   = (const float*)d_in[7];
    const int*   nfg  = (const int*)d_in[8];
    float* out = (float*)d_out;

    k_layer1<<<dim3(H1C/128, NPAIR/128), 256>>>(Maug, Q, W1, b1);
    k_cost  <<<NP, 256>>>(Maug, Q);
    k_layer2<<<dim3(H2C/128, NPAIR/128), 256>>>(W2, b2);
    k_layer3<<<NPAIR/8, 256>>>(W3, b3);
    k_reduce<<<MP, 512>>>(nfg, out);
}

// round 3
// speedup vs baseline: 5.9094x; 5.9094x over previous
#include <cuda_runtime.h>
#include <cuda_fp16.h>
#include <stdint.h>
#include <math.h>

#define NP 512
#define MP 512
#define DD 1024
#define H1C 512
#define H2C 256
#define NPAIR (NP*MP)
#define STRB 80   // smem bytes per 32-half row (64B data + 16B pad -> conflict-free ldmatrix)

// Scratch
__device__ __half g_h1[(size_t)NPAIR * H1C];   // 256 MB fp16 activations
__device__ __half g_w1h[H1C * DD];
__device__ __half g_w2h[H2C * H1C];
__device__ float  g_dpart[(size_t)NPAIR * 2];  // per-row logit partials (2 col-strips)
__device__ float  g_cost[NPAIR];

__device__ __forceinline__ float lrelu(float x){ return x >= 0.f ? x : 0.01f*x; }
__device__ __forceinline__ uint32_t smem_u32(const void* p){
    uint32_t a;
    asm("{ .reg .u64 t; cvta.to.shared.u64 t, %1; cvt.u32.u64 %0, t; }" : "=r"(a) : "l"(p));
    return a;
}
#define CP16(dst, src) asm volatile("cp.async.cg.shared.global [%0], [%1], 16;" :: "r"(dst), "l"(src))
#define CP_COMMIT() asm volatile("cp.async.commit_group;" ::: "memory")
#define CP_WAIT0()  asm volatile("cp.async.wait_group 0;" ::: "memory")

__device__ __forceinline__ void ldmat4(uint32_t* r, uint32_t addr){
    asm volatile("ldmatrix.sync.aligned.m8n8.x4.shared.b16 {%0,%1,%2,%3}, [%4];"
        : "=r"(r[0]),"=r"(r[1]),"=r"(r[2]),"=r"(r[3]) : "r"(addr));
}
__device__ __forceinline__ void mma_f16(float* c, const uint32_t* a, const uint32_t* b){
    asm volatile("mma.sync.aligned.m16n8k16.row.col.f32.f16.f16.f32 "
        "{%0,%1,%2,%3}, {%4,%5,%6,%7}, {%8,%9}, {%0,%1,%2,%3};"
        : "+f"(c[0]),"+f"(c[1]),"+f"(c[2]),"+f"(c[3])
        : "r"(a[0]),"r"(a[1]),"r"(a[2]),"r"(a[3]), "r"(b[0]),"r"(b[1]));
}

// Shared mainloop compute: CTA tile 128x128, warp tile 64x32, BK=32 (2 k16-steps)
__device__ __forceinline__ void compute_tile(uint32_t sa, uint32_t sb,
        int wm, int wn, int rA, int cAd, float acc[4][4][4]){
#pragma unroll
    for (int ks = 0; ks < 2; ks++){
        uint32_t a[4][4], b[4][2];
#pragma unroll
        for (int mt = 0; mt < 4; mt++)
            ldmat4(a[mt], sa + (uint32_t)((64*wm + 16*mt + rA)*STRB + (2*ks + cAd)*16));
#pragma unroll
        for (int p = 0; p < 2; p++){
            uint32_t r[4];
            ldmat4(r, sb + (uint32_t)((32*wn + 16*p + rA)*STRB + (2*ks + cAd)*16));
            b[2*p][0] = r[0]; b[2*p+1][0] = r[1];
            b[2*p][1] = r[2]; b[2*p+1][1] = r[3];
        }
#pragma unroll
        for (int mt = 0; mt < 4; mt++)
#pragma unroll
            for (int nt = 0; nt < 4; nt++)
                mma_f16(acc[mt][nt], a[mt], b[nt]);
    }
}

// ---------------------------------------------------------------------------
__global__ void k_conv(const float* __restrict__ W1, const float* __restrict__ W2){
    const int stride = gridDim.x * blockDim.x;
    const int i0 = blockIdx.x*blockDim.x + threadIdx.x;
    for (int i = i0; i < H1C*DD; i += stride) g_w1h[i] = __float2half(W1[i]);
    for (int i = i0; i < H2C*H1C; i += stride) g_w2h[i] = __float2half(W2[i]);
}

// ---------------------------------------------------------------------------
// Layer 1: GEMM [262144 x 512], K=1024.  A = diff^2 on the fly (+ fused cost).
// ---------------------------------------------------------------------------
__global__ __launch_bounds__(256,2) void k_layer1(
    const float* __restrict__ Maug, const float* __restrict__ Q,
    const float* __restrict__ b1)
{
    __shared__ __align__(16) char sAbuf[2][128*STRB];
    __shared__ __align__(16) char sBbuf[2][128*STRB];

    const int tid = threadIdx.x, lane = tid & 31, wid = tid >> 5;
    const int h0 = blockIdx.x * 128;
    const int r0 = blockIdx.y * 128;
    const int n  = r0 >> 9;
    const int m0 = r0 & 511;
    const int wm = wid >> 2, wn = wid & 3;
    const int rA = lane & 15, cAd = lane >> 4;
    const int kq = tid & 7,  rb  = tid >> 3;

    const uint32_t sAu[2] = { smem_u32(sAbuf[0]), smem_u32(sAbuf[1]) };
    const uint32_t sBu[2] = { smem_u32(sBbuf[0]), smem_u32(sBbuf[1]) };

    const float4* Q4 = (const float4*)Q;
    const float4* M4 = (const float4*)Maug;

    float acc[4][4][4];
#pragma unroll
    for (int i=0;i<4;i++)
#pragma unroll
    for (int j=0;j<4;j++)
#pragma unroll
    for (int k=0;k<4;k++) acc[i][j][k] = 0.f;
    float creg[4] = {0.f,0.f,0.f,0.f};

    auto genA = [&](int c, int buf){
        const float4 mv = M4[n*(DD/4) + c*8 + kq];
#pragma unroll
        for (int j = 0; j < 4; j++){
            const int row = rb + 32*j;
            const float4 q = Q4[(size_t)(m0 + row)*(DD/4) + c*8 + kq];
            float x0 = mv.x - q.x, x1 = mv.y - q.y, x2 = mv.z - q.z, x3 = mv.w - q.w;
            x0 *= x0; x1 *= x1; x2 *= x2; x3 *= x3;
            creg[j] += (x0 + x1) + (x2 + x3);
            char* p = sAbuf[buf] + row*STRB + kq*8;
            *(__half2*)(p)     = __floats2half2_rn(x0, x1);
            *(__half2*)(p + 4) = __floats2half2_rn(x2, x3);
        }
    };
    auto fillB = [&](int c, int buf){
#pragma unroll
        for (int jj = 0; jj < 2; jj++){
            const int idx = tid + 256*jj;
            const int row = idx >> 2, ch = idx & 3;
            CP16(sBu[buf] + (uint32_t)(row*STRB + ch*16),
                 g_w1h + (size_t)(h0 + row)*DD + c*32 + ch*8);
        }
    };

    genA(0, 0); fillB(0, 0); CP_COMMIT();
    for (int c = 0; c < 32; c++){
        const int buf = c & 1;
        CP_WAIT0(); __syncthreads();
        if (c + 1 < 32){ genA(c+1, buf^1); fillB(c+1, buf^1); CP_COMMIT(); }
        compute_tile(sAu[buf], sBu[buf], wm, wn, rA, cAd, acc);
    }

    // fused cost (fp32 exact), reduce over the 8 threads per row
#pragma unroll
    for (int j = 0; j < 4; j++){
        float v = creg[j];
        v += __shfl_xor_sync(0xffffffffu, v, 1);
        v += __shfl_xor_sync(0xffffffffu, v, 2);
        v += __shfl_xor_sync(0xffffffffu, v, 4);
        if (kq == 0 && blockIdx.x == 0)
            g_cost[n*MP + m0 + rb + 32*j] = v;
    }

    // epilogue: bias + leaky relu, store fp16
    const int g = lane >> 2, tg = lane & 3;
#pragma unroll
    for (int nt = 0; nt < 4; nt++){
        const int col = h0 + 32*wn + 8*nt + 2*tg;
        const float b0v = b1[col], b1v = b1[col+1];
#pragma unroll
        for (int mt = 0; mt < 4; mt++){
            const int row = r0 + 64*wm + 16*mt + g;
            *(__half2*)&g_h1[(size_t)row*H1C + col] =
                __floats2half2_rn(lrelu(acc[mt][nt][0]+b0v), lrelu(acc[mt][nt][1]+b1v));
            *(__half2*)&g_h1[(size_t)(row+8)*H1C + col] =
                __floats2half2_rn(lrelu(acc[mt][nt][2]+b0v), lrelu(acc[mt][nt][3]+b1v));
        }
    }
}

// ---------------------------------------------------------------------------
// Layer 2 (+3 fused): GEMM [262144 x 256], K=512; epilogue dots with W3 (fp32)
// and writes per-row partial logits (one per 128-col strip).
// ---------------------------------------------------------------------------
__global__ __launch_bounds__(256,2) void k_layer2(
    const float* __restrict__ b2, const float* __restrict__ W3)
{
    __shared__ __align__(16) char sAbuf[2][128*STRB];
    __shared__ __align__(16) char sBbuf[2][128*STRB];
    __shared__ float spart[128][4];

    const int tid = threadIdx.x, lane = tid & 31, wid = tid >> 5;
    const int h0 = blockIdx.x * 128;
    const int r0 = blockIdx.y * 128;
    const int wm = wid >> 2, wn = wid & 3;
    const int rA = lane & 15, cAd = lane >> 4;

    const uint32_t sAu[2] = { smem_u32(sAbuf[0]), smem_u32(sAbuf[1]) };
    const uint32_t sBu[2] = { smem_u32(sBbuf[0]), smem_u32(sBbuf[1]) };

    float acc[4][4][4];
#pragma unroll
    for (int i=0;i<4;i++)
#pragma unroll
    for (int j=0;j<4;j++)
#pragma unroll
    for (int k=0;k<4;k++) acc[i][j][k] = 0.f;

    auto fill = [&](int c, int buf){
#pragma unroll
        for (int jj = 0; jj < 2; jj++){
            const int idx = tid + 256*jj;
            const int row = idx >> 2, ch = idx & 3;
            CP16(sAu[buf] + (uint32_t)(row*STRB + ch*16),
                 g_h1 + (size_t)(r0 + row)*H1C + c*32 + ch*8);
            CP16(sBu[buf] + (uint32_t)(row*STRB + ch*16),
                 g_w2h + (size_t)(h0 + row)*H1C + c*32 + ch*8);
        }
    };

    fill(0, 0); CP_COMMIT();
    for (int c = 0; c < 16; c++){
        const int buf = c & 1;
        CP_WAIT0(); __syncthreads();
        if (c + 1 < 16){ fill(c+1, buf^1); CP_COMMIT(); }
        compute_tile(sAu[buf], sBu[buf], wm, wn, rA, cAd, acc);
    }

    // epilogue: bias + lrelu + W3 dot (fp32), per-row partial
    const int g = lane >> 2, tg = lane & 3;
    float dot[4][2];
#pragma unroll
    for (int mt=0; mt<4; mt++){ dot[mt][0]=0.f; dot[mt][1]=0.f; }
#pragma unroll
    for (int nt = 0; nt < 4; nt++){
        const int col = h0 + 32*wn + 8*nt + 2*tg;
        const float b0v = b2[col], b1v = b2[col+1];
        const float w0 = W3[col],  w1 = W3[col+1];
#pragma unroll
        for (int mt = 0; mt < 4; mt++){
            dot[mt][0] += lrelu(acc[mt][nt][0]+b0v)*w0 + lrelu(acc[mt][nt][1]+b1v)*w1;
            dot[mt][1] += lrelu(acc[mt][nt][2]+b0v)*w0 + lrelu(acc[mt][nt][3]+b1v)*w1;
        }
    }
#pragma unroll
    for (int mt = 0; mt < 4; mt++)
#pragma unroll
        for (int hh = 0; hh < 2; hh++){
            float v = dot[mt][hh];
            v += __shfl_xor_sync(0xffffffffu, v, 1);
            v += __shfl_xor_sync(0xffffffffu, v, 2);
            if (tg == 0) spart[64*wm + 16*mt + 8*hh + g][wn] = v;
        }
    __syncthreads();
    if (tid < 128){
        const float v = spart[tid][0] + spart[tid][1] + spart[tid][2] + spart[tid][3];
        g_dpart[(size_t)(r0 + tid)*2 + blockIdx.x] = v;
    }
}

// ---------------------------------------------------------------------------
// Softmax over n (per m) + weighted reductions
// ---------------------------------------------------------------------------
__global__ __launch_bounds__(512) void k_reduce(
    const int* __restrict__ nfg_p, const float* __restrict__ b3,
    float* __restrict__ out)
{
    __shared__ float sm[512];
    const int m = blockIdx.x, n = threadIdx.x;
    const int r = n*MP + m;
    const float v = -(g_dpart[(size_t)r*2] + g_dpart[(size_t)r*2 + 1] + b3[0]);

    sm[n] = v; __syncthreads();
    for (int s = 256; s; s >>= 1) {
        if (n < s) sm[n] = fmaxf(sm[n], sm[n + s]);
        __syncthreads();
    }
    const float mx = sm[0]; __syncthreads();

    const float p = expf(v - mx);
    sm[n] = p; __syncthreads();
    for (int s = 256; s; s >>= 1) {
        if (n < s) sm[n] += sm[n + s];
        __syncthreads();
    }
    const float Z = sm[0]; __syncthreads();

    const float sval = g_cost[r] * (p / Z);
    sm[n] = sval; __syncthreads();
    for (int s = 256; s; s >>= 1) {
        if (n < s) sm[n] += sm[n + s];
        __syncthreads();
    }
    const float score = sm[0]; __syncthreads();

    const int nfg = *nfg_p;
    sm[n] = (n < nfg) ? sval : 0.f; __syncthreads();
    for (int s = 256; s; s >>= 1) {
        if (n < s) sm[n] += sm[n + s];
        __syncthreads();
    }
    if (n == 0) {
        out[m]      = score;
        out[MP + m] = sm[0];
    }
}

// ---------------------------------------------------------------------------
extern "C" void kernel_launch(void* const* d_in, const int* in_sizes, int n_in,
                              void* d_out, int out_size)
{
    const float* Maug = (const float*)d_in[0];
    const float* Q    = (const float*)d_in[1];
    const float* W1   = (const float*)d_in[2];
    const float* b1   = (const float*)d_in[3];
    const float* W2   = (const float*)d_in[4];
    const float* b2   = (const float*)d_in[5];
    const float* W3   = (const float*)d_in[6];
    const float* b3   = (const float*)d_in[7];
    const int*   nfg  = (const int*)d_in[8];
    float* out = (float*)d_out;

    k_conv  <<<512, 256>>>(W1, W2);
    k_layer1<<<dim3(H1C/128, NPAIR/128), 256>>>(Maug, Q, b1);
    k_layer2<<<dim3(H2C/128, NPAIR/128), 256>>>(b2, W3);
    k_reduce<<<MP, 512>>>(nfg, b3, out);
}

// round 4
// speedup vs baseline: 6.2989x; 1.0659x over previous
#include <cuda_runtime.h>
#include <cuda_fp16.h>
#include <stdint.h>
#include <math.h>

#define NP 512
#define MP 512
#define DD 1024
#define H1C 512
#define H2C 256
#define NPAIR (NP*MP)
#define STRB 80   // bytes per 32-half smem row (64B data + 16B pad)

// Scratch
__device__ __half g_h1[(size_t)NPAIR * H1C];   // 256 MB fp16 activations
__device__ __half g_w1h[H1C * DD];
__device__ __half g_w2h[H2C * H1C];
__device__ float  g_d[NPAIR];                  // finished (negated) logits
__device__ float  g_cost[NPAIR];

__device__ __forceinline__ float lrelu(float x){ return x >= 0.f ? x : 0.01f*x; }
__device__ __forceinline__ uint32_t smem_u32(const void* p){
    uint32_t a;
    asm("{ .reg .u64 t; cvta.to.shared.u64 t, %1; cvt.u32.u64 %0, t; }" : "=r"(a) : "l"(p));
    return a;
}
#define CP16(dst, src) asm volatile("cp.async.cg.shared.global [%0], [%1], 16;" :: "r"(dst), "l"(src))
#define CP_COMMIT() asm volatile("cp.async.commit_group;" ::: "memory")
#define CP_WAIT2()  asm volatile("cp.async.wait_group 2;" ::: "memory")

__device__ __forceinline__ void ldmat4(uint32_t* r, uint32_t addr){
    asm volatile("ldmatrix.sync.aligned.m8n8.x4.shared.b16 {%0,%1,%2,%3}, [%4];"
        : "=r"(r[0]),"=r"(r[1]),"=r"(r[2]),"=r"(r[3]) : "r"(addr));
}
__device__ __forceinline__ void mma_f16(float* c, const uint32_t* a, const uint32_t* b){
    asm volatile("mma.sync.aligned.m16n8k16.row.col.f32.f16.f16.f32 "
        "{%0,%1,%2,%3}, {%4,%5,%6,%7}, {%8,%9}, {%0,%1,%2,%3};"
        : "+f"(c[0]),"+f"(c[1]),"+f"(c[2]),"+f"(c[3])
        : "r"(a[0]),"r"(a[1]),"r"(a[2]),"r"(a[3]), "r"(b[0]),"r"(b[1]));
}

// Mainloop compute: CTA 128x256, warp tile 64x64, BK=32 (2 k16-steps)
__device__ __forceinline__ void compute_tile64(uint32_t sa, uint32_t sb,
        int wm, int wn, int rA, int cAd, float acc[4][8][4]){
#pragma unroll
    for (int ks = 0; ks < 2; ks++){
        uint32_t a[4][4], b[8][2];
#pragma unroll
        for (int mt = 0; mt < 4; mt++)
            ldmat4(a[mt], sa + (uint32_t)((64*wm + 16*mt + rA)*STRB + (2*ks + cAd)*16));
#pragma unroll
        for (int p = 0; p < 4; p++){
            uint32_t r[4];
            ldmat4(r, sb + (uint32_t)((64*wn + 16*p + rA)*STRB + (2*ks + cAd)*16));
            b[2*p][0] = r[0]; b[2*p+1][0] = r[1];
            b[2*p][1] = r[2]; b[2*p+1][1] = r[3];
        }
#pragma unroll
        for (int mt = 0; mt < 4; mt++)
#pragma unroll
            for (int nt = 0; nt < 8; nt++)
                mma_f16(acc[mt][nt], a[mt], b[nt]);
    }
}

// ---------------------------------------------------------------------------
__global__ void k_conv(const float* __restrict__ W1, const float* __restrict__ W2){
    const int stride = gridDim.x * blockDim.x;
    const int i0 = blockIdx.x*blockDim.x + threadIdx.x;
    for (int i = i0; i < H1C*DD; i += stride) g_w1h[i] = __float2half(W1[i]);
    for (int i = i0; i < H2C*H1C; i += stride) g_w2h[i] = __float2half(W2[i]);
}

// ---------------------------------------------------------------------------
// Layer 1: GEMM [262144 x 512], K=1024.  CTA 128x256.  A = diff^2 on the fly.
// smem: A 2 x 10240  |  B 4 x 20480   (dynamic, 102400 B)
// ---------------------------------------------------------------------------
#define L1_SMEM (2*10240 + 4*20480)

__global__ __launch_bounds__(256,1) void k_layer1(
    const float* __restrict__ Maug, const float* __restrict__ Q,
    const float* __restrict__ b1)
{
    extern __shared__ __align__(16) char smem[];
    const int tid = threadIdx.x, lane = tid & 31, wid = tid >> 5;
    const int h0 = blockIdx.x * 256;
    const int r0 = blockIdx.y * 128;
    const int n  = r0 >> 9;
    const int m0 = r0 & 511;
    const int wm = wid & 1, wn = wid >> 1;
    const int rA = lane & 15, cAd = lane >> 4;
    const int kq = tid & 7,  rb  = tid >> 3;

    const uint32_t sbase = smem_u32(smem);
    const uint32_t sAu0 = sbase, sAu1 = sbase + 10240;
    const uint32_t sBu  = sbase + 20480;

    const float4* Q4 = (const float4*)Q;
    const float4* M4 = (const float4*)Maug;

    float acc[4][8][4];
#pragma unroll
    for (int i=0;i<4;i++)
#pragma unroll
    for (int j=0;j<8;j++)
#pragma unroll
    for (int k=0;k<4;k++) acc[i][j][k] = 0.f;
    float creg[4] = {0.f,0.f,0.f,0.f};

    float4 qv[4], mv;

    auto ldQ = [&](int c){
        mv = M4[n*(DD/4) + c*8 + kq];
#pragma unroll
        for (int j = 0; j < 4; j++)
            qv[j] = Q4[(size_t)(m0 + rb + 32*j)*(DD/4) + c*8 + kq];
    };
    auto stA = [&](uint32_t sAu){
#pragma unroll
        for (int j = 0; j < 4; j++){
            const int row = rb + 32*j;
            float x0 = mv.x - qv[j].x, x1 = mv.y - qv[j].y;
            float x2 = mv.z - qv[j].z, x3 = mv.w - qv[j].w;
            x0 *= x0; x1 *= x1; x2 *= x2; x3 *= x3;
            creg[j] += (x0 + x1) + (x2 + x3);
            char* p = smem + (sAu - sbase) + row*STRB + kq*8;
            *(__half2*)(p)     = __floats2half2_rn(x0, x1);
            *(__half2*)(p + 4) = __floats2half2_rn(x2, x3);
        }
    };
    auto fillB = [&](int c){
        const uint32_t s = sBu + (uint32_t)(c & 3) * 20480;
#pragma unroll
        for (int jj = 0; jj < 4; jj++){
            const int idx = tid + 256*jj;
            const int row = idx >> 2, ch = idx & 3;
            CP16(s + (uint32_t)(row*STRB + ch*16),
                 g_w1h + (size_t)(h0 + row)*DD + c*32 + ch*8);
        }
    };

    ldQ(0); stA(sAu0);
    fillB(0); CP_COMMIT();
    fillB(1); CP_COMMIT();
    fillB(2); CP_COMMIT();

    for (int c = 0; c < 32; c++){
        const uint32_t sa = (c & 1) ? sAu1 : sAu0;
        if (c + 1 < 32) ldQ(c + 1);          // prefetch Q for next chunk
        CP_WAIT2(); __syncthreads();
        compute_tile64(sa, sBu + (uint32_t)(c & 3)*20480, wm, wn, rA, cAd, acc);
        if (c + 1 < 32) stA((c & 1) ? sAu0 : sAu1);
        if (c + 3 < 32) fillB(c + 3);
        CP_COMMIT();
    }

    // fused cost (fp32 exact), reduce over the 8 threads per row
#pragma unroll
    for (int j = 0; j < 4; j++){
        float v = creg[j];
        v += __shfl_xor_sync(0xffffffffu, v, 1);
        v += __shfl_xor_sync(0xffffffffu, v, 2);
        v += __shfl_xor_sync(0xffffffffu, v, 4);
        if (kq == 0 && blockIdx.x == 0)
            g_cost[n*MP + m0 + rb + 32*j] = v;
    }

    // epilogue: bias + leaky relu, store fp16
    const int g = lane >> 2, tg = lane & 3;
#pragma unroll
    for (int nt = 0; nt < 8; nt++){
        const int col = h0 + 64*wn + 8*nt + 2*tg;
        const float b0v = b1[col], b1v = b1[col+1];
#pragma unroll
        for (int mt = 0; mt < 4; mt++){
            const int row = r0 + 64*wm + 16*mt + g;
            *(__half2*)&g_h1[(size_t)row*H1C + col] =
                __floats2half2_rn(lrelu(acc[mt][nt][0]+b0v), lrelu(acc[mt][nt][1]+b1v));
            *(__half2*)&g_h1[(size_t)(row+8)*H1C + col] =
                __floats2half2_rn(lrelu(acc[mt][nt][2]+b0v), lrelu(acc[mt][nt][3]+b1v));
        }
    }
}

// ---------------------------------------------------------------------------
// Layer 2+3: GEMM [262144 x 256], K=512, CTA 128x256 (full N).  Epilogue
// applies bias+lrelu, dots with W3, writes finished negated logit.
// smem: A 4 x 10240 | B 4 x 20480  (dynamic, 122880 B)
// ---------------------------------------------------------------------------
#define L2_SMEM (4*10240 + 4*20480)

__global__ __launch_bounds__(256,1) void k_layer2(
    const float* __restrict__ b2, const float* __restrict__ W3,
    const float* __restrict__ b3)
{
    extern __shared__ __align__(16) char smem[];
    const int tid = threadIdx.x, lane = tid & 31, wid = tid >> 5;
    const int r0 = blockIdx.x * 128;
    const int wm = wid & 1, wn = wid >> 1;
    const int rA = lane & 15, cAd = lane >> 4;

    const uint32_t sbase = smem_u32(smem);
    const uint32_t sAu = sbase;
    const uint32_t sBu = sbase + 4*10240;

    float acc[4][8][4];
#pragma unroll
    for (int i=0;i<4;i++)
#pragma unroll
    for (int j=0;j<8;j++)
#pragma unroll
    for (int k=0;k<4;k++) acc[i][j][k] = 0.f;

    auto fill = [&](int c){
        const uint32_t st = (uint32_t)(c & 3);
        const uint32_t sa = sAu + st*10240, sb = sBu + st*20480;
        // A: h1 tile 128x32 (512 float4)
#pragma unroll
        for (int jj = 0; jj < 2; jj++){
            const int idx = tid + 256*jj;
            const int row = idx >> 2, ch = idx & 3;
            CP16(sa + (uint32_t)(row*STRB + ch*16),
                 g_h1 + (size_t)(r0 + row)*H1C + c*32 + ch*8);
        }
        // B: W2 tile 256x32 (1024 float4)
#pragma unroll
        for (int jj = 0; jj < 4; jj++){
            const int idx = tid + 256*jj;
            const int row = idx >> 2, ch = idx & 3;
            CP16(sb + (uint32_t)(row*STRB + ch*16),
                 g_w2h + (size_t)row*H1C + c*32 + ch*8);
        }
    };

    fill(0); CP_COMMIT();
    fill(1); CP_COMMIT();
    fill(2); CP_COMMIT();

    for (int c = 0; c < 16; c++){
        const uint32_t st = (uint32_t)(c & 3);
        CP_WAIT2(); __syncthreads();
        compute_tile64(sAu + st*10240, sBu + st*20480, wm, wn, rA, cAd, acc);
        if (c + 3 < 16) fill(c + 3);
        CP_COMMIT();
    }

    // epilogue: bias + lrelu + W3 dot (fp32)
    const int g = lane >> 2, tg = lane & 3;
    float dot[4][2];
#pragma unroll
    for (int mt=0; mt<4; mt++){ dot[mt][0]=0.f; dot[mt][1]=0.f; }
#pragma unroll
    for (int nt = 0; nt < 8; nt++){
        const int col = 64*wn + 8*nt + 2*tg;
        const float b0v = b2[col], b1v = b2[col+1];
        const float w0 = W3[col],  w1 = W3[col+1];
#pragma unroll
        for (int mt = 0; mt < 4; mt++){
            dot[mt][0] += lrelu(acc[mt][nt][0]+b0v)*w0 + lrelu(acc[mt][nt][1]+b1v)*w1;
            dot[mt][1] += lrelu(acc[mt][nt][2]+b0v)*w0 + lrelu(acc[mt][nt][3]+b1v)*w1;
        }
    }
    // reduce across tg (shfl) then across the 4 wn warps (smem)
    float* spart = (float*)smem;   // [128][4] — safe: disjoint from in-flight stages
#pragma unroll
    for (int mt = 0; mt < 4; mt++)
#pragma unroll
        for (int hh = 0; hh < 2; hh++){
            float v = dot[mt][hh];
            v += __shfl_xor_sync(0xffffffffu, v, 1);
            v += __shfl_xor_sync(0xffffffffu, v, 2);
            if (tg == 0) spart[(64*wm + 16*mt + 8*hh + g)*4 + wn] = v;
        }
    __syncthreads();
    if (tid < 128){
        const float v = spart[tid*4+0] + spart[tid*4+1] + spart[tid*4+2] + spart[tid*4+3];
        g_d[r0 + tid] = -(v + b3[0]);
    }
}

// ---------------------------------------------------------------------------
// Softmax over n (per m) + weighted reductions
// ---------------------------------------------------------------------------
__global__ __launch_bounds__(512) void k_reduce(
    const int* __restrict__ nfg_p, float* __restrict__ out)
{
    __shared__ float sm[512];
    const int m = blockIdx.x, n = threadIdx.x;
    const float v = g_d[n * MP + m];

    sm[n] = v; __syncthreads();
    for (int s = 256; s; s >>= 1) {
        if (n < s) sm[n] = fmaxf(sm[n], sm[n + s]);
        __syncthreads();
    }
    const float mx = sm[0]; __syncthreads();

    const float p = expf(v - mx);
    sm[n] = p; __syncthreads();
    for (int s = 256; s; s >>= 1) {
        if (n < s) sm[n] += sm[n + s];
        __syncthreads();
    }
    const float Z = sm[0]; __syncthreads();

    const float sval = g_cost[n * MP + m] * (p / Z);
    sm[n] = sval; __syncthreads();
    for (int s = 256; s; s >>= 1) {
        if (n < s) sm[n] += sm[n + s];
        __syncthreads();
    }
    const float score = sm[0]; __syncthreads();

    const int nfg = *nfg_p;
    sm[n] = (n < nfg) ? sval : 0.f; __syncthreads();
    for (int s = 256; s; s >>= 1) {
        if (n < s) sm[n] += sm[n + s];
        __syncthreads();
    }
    if (n == 0) {
        out[m]      = score;
        out[MP + m] = sm[0];
    }
}

// ---------------------------------------------------------------------------
extern "C" void kernel_launch(void* const* d_in, const int* in_sizes, int n_in,
                              void* d_out, int out_size)
{
    const float* Maug = (const float*)d_in[0];
    const float* Q    = (const float*)d_in[1];
    const float* W1   = (const float*)d_in[2];
    const float* b1   = (const float*)d_in[3];
    const float* W2   = (const float*)d_in[4];
    const float* b2   = (const float*)d_in[5];
    const float* W3   = (const float*)d_in[6];
    const float* b3   = (const float*)d_in[7];
    const int*   nfg  = (const int*)d_in[8];
    float* out = (float*)d_out;

    cudaFuncSetAttribute(k_layer1, cudaFuncAttributeMaxDynamicSharedMemorySize, L1_SMEM);
    cudaFuncSetAttribute(k_layer2, cudaFuncAttributeMaxDynamicSharedMemorySize, L2_SMEM);

    k_conv  <<<512, 256>>>(W1, W2);
    k_layer1<<<dim3(H1C/256, NPAIR/128), 256, L1_SMEM>>>(Maug, Q, b1);
    k_layer2<<<NPAIR/128, 256, L2_SMEM>>>(b2, W3, b3);
    k_reduce<<<MP, 512>>>(nfg, out);
}